// round 1
// baseline (speedup 1.0000x reference)
#include <cuda_runtime.h>
#include <math.h>
#include <stdint.h>

// Problem constants (fixed for this problem instance)
#define BB 64
#define RR 8192
#define DD 256

static __device__ __constant__ float c_dummy; // (unused)

#define EPS_NORM 1e-12f
#define EPS_SUM  1e-8f

// ---------------- device scratch (no allocations allowed) ----------------
__device__ float g_qn[BB * DD];        // normalized query reps
__device__ int   g_q[BB];              // clipped query indices
__device__ float g_params[4];          // thr, strength, temp, scale
__device__ float g_sims[BB * RR];      // cosine sims
__device__ int   g_count[BB];          // # masked entries per batch
__device__ int   g_idx[BB * RR];       // compacted indices
__device__ float g_w[BB * RR];         // compacted normalized weights

__device__ __forceinline__ float sigmoid_acc(float x) {
    return 1.0f / (1.0f + expf(-x));
}

// ---------------- kernel A: query-row norm + params ----------------
__global__ void kA(const float* __restrict__ reps,
                   const long long* __restrict__ qr,
                   const float* __restrict__ thrp,
                   const float* __restrict__ strp,
                   const float* __restrict__ scalep,
                   const float* __restrict__ tempp)
{
    int b = blockIdx.x;
    int t = threadIdx.x;  // 256 threads == DD

    long long qq = qr[b];
    int q = (int)(qq < 0 ? 0 : (qq > (RR - 1) ? (RR - 1) : qq));

    float v = reps[((size_t)b * RR + q) * DD + t];

    // block sum of v*v over 256 threads
    __shared__ float sred[8];
    float s = v * v;
    #pragma unroll
    for (int o = 16; o > 0; o >>= 1) s += __shfl_xor_sync(0xffffffffu, s, o);
    if ((t & 31) == 0) sred[t >> 5] = s;
    __syncthreads();
    if (t < 8) {
        float x = sred[t];
        #pragma unroll
        for (int o = 4; o > 0; o >>= 1) x += __shfl_xor_sync(0xffu, x, o);
        if (t == 0) sred[0] = x;
    }
    __syncthreads();
    float nrm = sqrtf(sred[0]);
    g_qn[b * DD + t] = v / fmaxf(nrm, EPS_NORM);

    if (t == 0) {
        g_q[b] = q;
        if (b == 0) {
            g_params[0] = sigmoid_acc(thrp[0]);                       // threshold
            g_params[1] = sigmoid_acc(strp[0]) * 0.2f;                // strength
            g_params[2] = fminf(fmaxf(tempp[0], 0.1f), 10.0f);        // temp
            g_params[3] = scalep[0];                                  // scale
        }
    }
}

// ---------------- kernel B: fused copy + cosine sims ----------------
// One warp per row (D=256 floats = 64 float4; lane handles f4[lane], f4[lane+32]).
// Block = 256 threads (8 warps), each warp does 4 rows -> 32 rows per block.
// Grid = BB * (RR/32) = 64 * 256 = 16384 blocks.
__global__ void __launch_bounds__(256) kB(const float* __restrict__ in,
                                          float* __restrict__ out)
{
    const int warp = threadIdx.x >> 5;
    const int lane = threadIdx.x & 31;
    const int b = blockIdx.x >> 8;                 // 256 blocks per batch
    const int rowBase = (blockIdx.x & 255) * 32;

    const float4* qn4 = (const float4*)(g_qn + b * DD);
    const float4 q0 = qn4[lane];
    const float4 q1 = qn4[lane + 32];
    const int q = g_q[b];

    #pragma unroll
    for (int i = 0; i < 4; i++) {
        int row = rowBase + warp * 4 + i;
        size_t off4 = ((size_t)b * RR + row) * (DD / 4);
        const float4* ip = (const float4*)in + off4;
        float4* op = (float4*)out + off4;

        float4 v0 = __ldcs(ip + lane);
        float4 v1 = __ldcs(ip + lane + 32);
        __stcs(op + lane, v0);
        __stcs(op + lane + 32, v1);

        float ss = v0.x*v0.x + v0.y*v0.y + v0.z*v0.z + v0.w*v0.w
                 + v1.x*v1.x + v1.y*v1.y + v1.z*v1.z + v1.w*v1.w;
        float dp = v0.x*q0.x + v0.y*q0.y + v0.z*q0.z + v0.w*q0.w
                 + v1.x*q1.x + v1.y*q1.y + v1.z*q1.z + v1.w*q1.w;

        #pragma unroll
        for (int o = 16; o > 0; o >>= 1) {
            ss += __shfl_xor_sync(0xffffffffu, ss, o);
            dp += __shfl_xor_sync(0xffffffffu, dp, o);
        }
        if (lane == 0) {
            float sim = dp / fmaxf(sqrtf(ss), EPS_NORM);
            g_sims[(size_t)b * RR + row] = (row == q) ? -1.0f : sim;
        }
    }
}

// ---------------- kernel C: per-batch masked softmax + weights + compaction ----
// One block per batch, 256 threads, each thread owns 32 contiguous sims.
__global__ void __launch_bounds__(256) kC()
{
    const int b = blockIdx.x;
    const int t = threadIdx.x;

    __shared__ float s_sims[RR];         // 32 KB
    __shared__ float s_red[8];
    __shared__ int   s_cnt[256];
    __shared__ float s_bc[2];            // broadcast: M (maxlogit), ES / AS

    const float thr   = g_params[0];
    const float temp  = g_params[2];
    const float scale = g_params[3];

    for (int i = t; i < RR; i += 256)
        s_sims[i] = g_sims[(size_t)b * RR + i];
    __syncthreads();

    const int base = t * 32;

    // pass 1: local max over masked + local count
    float m = -3.0e38f;
    int cnt = 0;
    #pragma unroll
    for (int j = 0; j < 32; j++) {
        float s = s_sims[base + j];
        if (s > thr) { m = fmaxf(m, s); cnt++; }
    }
    // block max
    {
        float x = m;
        #pragma unroll
        for (int o = 16; o > 0; o >>= 1) x = fmaxf(x, __shfl_xor_sync(0xffffffffu, x, o));
        if ((t & 31) == 0) s_red[t >> 5] = x;
        __syncthreads();
        if (t < 8) {
            float y = s_red[t];
            #pragma unroll
            for (int o = 4; o > 0; o >>= 1) y = fmaxf(y, __shfl_xor_sync(0xffu, y, o));
            if (t == 0) s_bc[0] = y;
        }
        __syncthreads();
    }
    // block total count (also needed for has_valid)
    // inclusive scan over s_cnt for deterministic compaction offsets
    s_cnt[t] = cnt;
    __syncthreads();
    int x = cnt;
    for (int off = 1; off < 256; off <<= 1) {
        int y = (t >= off) ? s_cnt[t - off] : 0;
        __syncthreads();
        x += y;
        s_cnt[t] = x;
        __syncthreads();
    }
    const int total = s_cnt[255];
    const int myOff = x - cnt;   // exclusive offset

    if (total == 0) {
        if (t == 0) g_count[b] = 0;
        return;
    }

    const float M = s_bc[0] / temp;  // max logit (temp > 0, monotone)

    // pass 2: expsum over masked
    float es = 0.0f;
    #pragma unroll
    for (int j = 0; j < 32; j++) {
        float s = s_sims[base + j];
        if (s > thr) es += expf(s / temp - M);
    }
    {
        float xx = es;
        #pragma unroll
        for (int o = 16; o > 0; o >>= 1) xx += __shfl_xor_sync(0xffffffffu, xx, o);
        if ((t & 31) == 0) s_red[t >> 5] = xx;
        __syncthreads();
        if (t < 8) {
            float y = s_red[t];
            #pragma unroll
            for (int o = 4; o > 0; o >>= 1) y += __shfl_xor_sync(0xffu, y, o);
            if (t == 0) s_bc[1] = y;
        }
        __syncthreads();
    }
    const float ES = s_bc[1];

    // pass 3: adjusted sum over masked
    float as = 0.0f;
    #pragma unroll
    for (int j = 0; j < 32; j++) {
        float s = s_sims[base + j];
        if (s > thr) {
            float soft  = expf(s / temp - M) / ES;
            float sim_w = 1.0f / (1.0f + expf(-(s - thr) * 10.0f));
            as += soft * sim_w * (1.0f + scale * s);
        }
    }
    __syncthreads();
    {
        float xx = as;
        #pragma unroll
        for (int o = 16; o > 0; o >>= 1) xx += __shfl_xor_sync(0xffffffffu, xx, o);
        if ((t & 31) == 0) s_red[t >> 5] = xx;
        __syncthreads();
        if (t < 8) {
            float y = s_red[t];
            #pragma unroll
            for (int o = 4; o > 0; o >>= 1) y += __shfl_xor_sync(0xffu, y, o);
            if (t == 0) s_bc[1] = y;
        }
        __syncthreads();
    }
    const float inv = 1.0f / (s_bc[1] + EPS_SUM);

    // write compacted (deterministic order: sorted by r)
    int pos = myOff;
    #pragma unroll
    for (int j = 0; j < 32; j++) {
        float s = s_sims[base + j];
        if (s > thr) {
            float soft  = expf(s / temp - M) / ES;
            float sim_w = 1.0f / (1.0f + expf(-(s - thr) * 10.0f));
            float a = soft * sim_w * (1.0f + scale * s) * inv;
            g_idx[(size_t)b * RR + pos] = base + j;
            g_w  [(size_t)b * RR + pos] = a;
            pos++;
        }
    }
    if (t == 0) g_count[b] = total;
}

// ---------------- kernel D: epilogue (rewrite row q if any valid) ----------------
__global__ void __launch_bounds__(256) kD(const float* __restrict__ reps,
                                          float* __restrict__ out)
{
    const int b = blockIdx.x;
    const int d = threadIdx.x;   // 256 == DD

    const int count = g_count[b];
    if (count == 0) return;      // output row q already == qrep from kB copy

    const int q = g_q[b];
    const float strength = g_params[1];

    float acc = 0.0f;
    for (int i = 0; i < count; i++) {
        int r  = g_idx[(size_t)b * RR + i];
        float w = g_w[(size_t)b * RR + i];
        acc += w * reps[((size_t)b * RR + r) * DD + d];
    }
    float qv = reps[((size_t)b * RR + q) * DD + d];
    out[((size_t)b * RR + q) * DD + d] = (1.0f - strength) * qv + strength * acc;
}

// ---------------- launch ----------------
extern "C" void kernel_launch(void* const* d_in, const int* in_sizes, int n_in,
                              void* d_out, int out_size)
{
    const float*     reps  = (const float*)d_in[0];
    const long long* qrels = (const long long*)d_in[1];
    const float*     thrp  = (const float*)d_in[2];
    const float*     strp  = (const float*)d_in[3];
    const float*     sclp  = (const float*)d_in[4];
    const float*     tmpp  = (const float*)d_in[5];
    float* out = (float*)d_out;

    kA<<<BB, DD>>>(reps, qrels, thrp, strp, sclp, tmpp);
    kB<<<BB * (RR / 32), 256>>>(reps, out);
    kC<<<BB, 256>>>();
    kD<<<BB, DD>>>(reps, out);
}

// round 2
// speedup vs baseline: 1.0185x; 1.0185x over previous
#include <cuda_runtime.h>
#include <math.h>
#include <stdint.h>

#define BB 64
#define RR 8192
#define DD 256

#define EPS_NORM 1e-12f
#define EPS_SUM  1e-8f

// ---------------- device scratch (no allocations allowed) ----------------
__device__ float g_sims[BB * RR];      // cosine sims
__device__ int   g_idx[BB * RR];       // compacted indices (per-batch scratch)
__device__ float g_w[BB * RR];         // compacted normalized weights

__device__ __forceinline__ float sigmoid_acc(float x) {
    return 1.0f / (1.0f + expf(-x));
}

__device__ __forceinline__ int clip_q(long long qq) {
    return (int)(qq < 0 ? 0 : (qq > (RR - 1) ? (RR - 1) : qq));
}

// ---------------- kernel B: fused qnorm + copy + cosine sims ----------------
// Each block: 256 threads = 8 warps. Block normalizes the query row (1 KB,
// L2-resident after first touch), then each warp streams 4 rows:
// copy in->out (__ldcs/__stcs, evict-first) + cosine sim via warp reduce.
// Grid = BB * (RR/32) = 16384 blocks.
__global__ void __launch_bounds__(256) kB(const float* __restrict__ in,
                                          float* __restrict__ out,
                                          const long long* __restrict__ qrels)
{
    __shared__ float s_qn[DD];
    __shared__ float s_red[8];

    const int t    = threadIdx.x;
    const int warp = t >> 5;
    const int lane = t & 31;
    const int b = blockIdx.x >> 8;                 // 256 blocks per batch
    const int rowBase = (blockIdx.x & 255) * 32;

    const int q = clip_q(qrels[b]);

    // --- per-block query-row normalization (redundant across blocks, cheap) ---
    float v = in[((size_t)b * RR + q) * DD + t];
    float s = v * v;
    #pragma unroll
    for (int o = 16; o > 0; o >>= 1) s += __shfl_xor_sync(0xffffffffu, s, o);
    if (lane == 0) s_red[warp] = s;
    __syncthreads();
    if (t < 8) {
        float x = s_red[t];
        #pragma unroll
        for (int o = 4; o > 0; o >>= 1) x += __shfl_xor_sync(0xffu, x, o);
        if (t == 0) s_red[0] = x;
    }
    __syncthreads();
    const float invn = 1.0f / fmaxf(sqrtf(s_red[0]), EPS_NORM);
    s_qn[t] = v * invn;
    __syncthreads();

    const float4* qn4 = (const float4*)s_qn;
    const float4 q0 = qn4[lane];
    const float4 q1 = qn4[lane + 32];

    #pragma unroll
    for (int i = 0; i < 4; i++) {
        int row = rowBase + warp * 4 + i;
        size_t off4 = ((size_t)b * RR + row) * (DD / 4);
        const float4* ip = (const float4*)in + off4;
        float4* op = (float4*)out + off4;

        float4 v0 = __ldcs(ip + lane);
        float4 v1 = __ldcs(ip + lane + 32);
        __stcs(op + lane, v0);
        __stcs(op + lane + 32, v1);

        float ss = v0.x*v0.x + v0.y*v0.y + v0.z*v0.z + v0.w*v0.w
                 + v1.x*v1.x + v1.y*v1.y + v1.z*v1.z + v1.w*v1.w;
        float dp = v0.x*q0.x + v0.y*q0.y + v0.z*q0.z + v0.w*q0.w
                 + v1.x*q1.x + v1.y*q1.y + v1.z*q1.z + v1.w*q1.w;

        #pragma unroll
        for (int o = 16; o > 0; o >>= 1) {
            ss += __shfl_xor_sync(0xffffffffu, ss, o);
            dp += __shfl_xor_sync(0xffffffffu, dp, o);
        }
        if (lane == 0) {
            float sim = dp / fmaxf(sqrtf(ss), EPS_NORM);
            g_sims[(size_t)b * RR + row] = (row == q) ? -1.0f : sim;
        }
    }
}

// ---------------- kernel CD: masked softmax + weights + compaction + epilogue ----
// One block per batch, 256 threads, each thread owns 32 contiguous sims.
__global__ void __launch_bounds__(256) kCD(const float* __restrict__ reps,
                                           float* __restrict__ out,
                                           const long long* __restrict__ qrels,
                                           const float* __restrict__ thrp,
                                           const float* __restrict__ strp,
                                           const float* __restrict__ scalep,
                                           const float* __restrict__ tempp)
{
    const int b = blockIdx.x;
    const int t = threadIdx.x;

    __shared__ float s_sims[RR];         // 32 KB
    __shared__ float s_red[8];
    __shared__ int   s_cnt[256];
    __shared__ float s_bc[2];

    const float thr      = sigmoid_acc(thrp[0]);
    const float strength = sigmoid_acc(strp[0]) * 0.2f;
    const float temp     = fminf(fmaxf(tempp[0], 0.1f), 10.0f);
    const float scale    = scalep[0];
    const int   q        = clip_q(qrels[b]);

    for (int i = t; i < RR; i += 256)
        s_sims[i] = g_sims[(size_t)b * RR + i];
    __syncthreads();

    const int base = t * 32;

    // pass 1: local max over masked + local count
    float m = -3.0e38f;
    int cnt = 0;
    #pragma unroll
    for (int j = 0; j < 32; j++) {
        float s = s_sims[base + j];
        if (s > thr) { m = fmaxf(m, s); cnt++; }
    }
    // block max
    {
        float x = m;
        #pragma unroll
        for (int o = 16; o > 0; o >>= 1) x = fmaxf(x, __shfl_xor_sync(0xffffffffu, x, o));
        if ((t & 31) == 0) s_red[t >> 5] = x;
        __syncthreads();
        if (t < 8) {
            float y = s_red[t];
            #pragma unroll
            for (int o = 4; o > 0; o >>= 1) y = fmaxf(y, __shfl_xor_sync(0xffu, y, o));
            if (t == 0) s_bc[0] = y;
        }
        __syncthreads();
    }
    // inclusive scan of counts for deterministic compaction offsets
    s_cnt[t] = cnt;
    __syncthreads();
    int x = cnt;
    for (int off = 1; off < 256; off <<= 1) {
        int y = (t >= off) ? s_cnt[t - off] : 0;
        __syncthreads();
        x += y;
        s_cnt[t] = x;
        __syncthreads();
    }
    const int total = s_cnt[255];
    const int myOff = x - cnt;   // exclusive offset

    if (total == 0) return;      // out row q already == qrep (kB copy)

    const float M = s_bc[0] / temp;

    // pass 2: expsum over masked
    float es = 0.0f;
    #pragma unroll
    for (int j = 0; j < 32; j++) {
        float s = s_sims[base + j];
        if (s > thr) es += expf(s / temp - M);
    }
    {
        float xx = es;
        #pragma unroll
        for (int o = 16; o > 0; o >>= 1) xx += __shfl_xor_sync(0xffffffffu, xx, o);
        if ((t & 31) == 0) s_red[t >> 5] = xx;
        __syncthreads();
        if (t < 8) {
            float y = s_red[t];
            #pragma unroll
            for (int o = 4; o > 0; o >>= 1) y += __shfl_xor_sync(0xffu, y, o);
            if (t == 0) s_bc[1] = y;
        }
        __syncthreads();
    }
    const float ES = s_bc[1];

    // pass 3: adjusted sum over masked
    float as = 0.0f;
    #pragma unroll
    for (int j = 0; j < 32; j++) {
        float s = s_sims[base + j];
        if (s > thr) {
            float soft  = expf(s / temp - M) / ES;
            float sim_w = 1.0f / (1.0f + expf(-(s - thr) * 10.0f));
            as += soft * sim_w * (1.0f + scale * s);
        }
    }
    __syncthreads();
    {
        float xx = as;
        #pragma unroll
        for (int o = 16; o > 0; o >>= 1) xx += __shfl_xor_sync(0xffffffffu, xx, o);
        if ((t & 31) == 0) s_red[t >> 5] = xx;
        __syncthreads();
        if (t < 8) {
            float y = s_red[t];
            #pragma unroll
            for (int o = 4; o > 0; o >>= 1) y += __shfl_xor_sync(0xffu, y, o);
            if (t == 0) s_bc[1] = y;
        }
        __syncthreads();
    }
    const float inv = 1.0f / (s_bc[1] + EPS_SUM);

    // compaction (deterministic: sorted by r) into per-batch global scratch
    int pos = myOff;
    #pragma unroll
    for (int j = 0; j < 32; j++) {
        float s = s_sims[base + j];
        if (s > thr) {
            float soft  = expf(s / temp - M) / ES;
            float sim_w = 1.0f / (1.0f + expf(-(s - thr) * 10.0f));
            float a = soft * sim_w * (1.0f + scale * s) * inv;
            g_idx[(size_t)b * RR + pos] = base + j;
            g_w  [(size_t)b * RR + pos] = a;
            pos++;
        }
    }
    __syncthreads();   // makes this block's global writes visible block-wide

    // ---- inline epilogue: rewrite row q ----
    const int d = t;   // 256 == DD
    float acc = 0.0f;
    for (int i = 0; i < total; i++) {
        int   r = g_idx[(size_t)b * RR + i];
        float w = g_w [(size_t)b * RR + i];
        acc += w * reps[((size_t)b * RR + r) * DD + d];
    }
    float qv = reps[((size_t)b * RR + q) * DD + d];
    out[((size_t)b * RR + q) * DD + d] = (1.0f - strength) * qv + strength * acc;
}

// ---------------- launch ----------------
extern "C" void kernel_launch(void* const* d_in, const int* in_sizes, int n_in,
                              void* d_out, int out_size)
{
    const float*     reps  = (const float*)d_in[0];
    const long long* qrels = (const long long*)d_in[1];
    const float*     thrp  = (const float*)d_in[2];
    const float*     strp  = (const float*)d_in[3];
    const float*     sclp  = (const float*)d_in[4];
    const float*     tmpp  = (const float*)d_in[5];
    float* out = (float*)d_out;

    kB<<<BB * (RR / 32), 256>>>(reps, out, qrels);
    kCD<<<BB, 256>>>(reps, out, qrels, thrp, strp, sclp, tmpp);
}